// round 14
// baseline (speedup 1.0000x reference)
#include <cuda_runtime.h>
#include <cuda_fp16.h>
#include <cstdint>
#include <cstddef>

#define BATCH   2048
#define OBS_N   8
#define PRED_N  12
#define HID     512
#define G4      2048
#define NSTEPS  19
#define OBSTEPS 7
#define BH      (BATCH*HID)

// fp16 fragment-packed image geometry (BK = 64)
#define ABLKH   8192
#define ABLKB   16384u
#define AIMGH   (16*8*ABLKH)
#define BBLKH   16384
#define BBLKB   32768u
#define WIMGH   (8*16*BBLKH)
#define NPART   32

// ---------------- scratch ----------------
__device__ __align__(1024) __half g_H[4 * AIMGH];     // [buf(2)][layer(2)]
__device__ __align__(1024) __half g_Wp[2 * WIMGH];
__device__ float g_M[3 * G4];                         // M0,M1,c0 (permuted rows)
__device__ float g_v01[OBSTEPS * BATCH * 2];          // normalized inputs per (t,b)
__device__ float g_c[2 * BH];
__device__ float g_bias[2 * G4];
__device__ float g_velp[NPART * BATCH * PRED_N * 2];  // decode partials [part][b][k][d]

// ---------------- helpers ----------------
__device__ __forceinline__ uint32_t smem_u32(const void* p) {
    uint32_t a;
    asm("{ .reg .u64 t; cvta.to.shared.u64 t, %1; cvt.u32.u64 %0, t; }" : "=r"(a) : "l"(p));
    return a;
}
__device__ __forceinline__ float fsigm(float x) {
    return __fdividef(1.0f, 1.0f + __expf(-x));
}
__device__ __forceinline__ float ftanh(float x) {
    float a = fabsf(x);
    float t = 1.0f - __fdividef(2.0f, __expf(2.0f * a) + 1.0f);
    return copysignf(t, x);
}
// A (m16n8k16 row-major) half-index within a 128x64 block (tile = 256 halfs)
__device__ __forceinline__ int a_off_h(int row, int k) {
    int mi = row >> 4, r = row & 15;
    int ki = k >> 4,  kk = k & 15;
    int tile = ki * 8 + mi;
    int lane = (r & 7) * 4 + ((kk & 7) >> 1);
    int sel  = ((r >> 3) & 1) + ((kk >> 3) << 1);
    return tile * 256 + lane * 8 + sel * 2 + (kk & 1);
}
// B (m16n8k16 col) half-index within a 256x64 block, k32-paired per uint4
__device__ __forceinline__ int b_off_h(int rn, int k) {
    int kp = k >> 5, k32 = k & 31;
    int ki_in = k32 >> 4, kk = k32 & 15;
    int tile = kp * 32 + (rn >> 3);
    int lane = (rn & 7) * 4 + ((kk & 7) >> 1);
    int sel  = ki_in * 2 + (kk >> 3);
    return tile * 256 + lane * 8 + sel * 2 + (kk & 1);
}

#define MBARRIER_INIT(addr, cnt) \
    asm volatile("mbarrier.init.shared.b64 [%0], %1;" :: "r"(addr), "r"(cnt) : "memory")
#define MBARRIER_INVAL(addr) \
    asm volatile("mbarrier.inval.shared.b64 [%0];" :: "r"(addr) : "memory")
#define MBARRIER_EXPECT_TX(addr, bytes) \
    asm volatile("mbarrier.arrive.expect_tx.shared.b64 _, [%0], %1;" :: "r"(addr), "r"(bytes) : "memory")
#define MBARRIER_WAIT_PARITY(addr, ph) do {                                   \
    uint32_t _m = (addr), _p = (ph), _d;                                      \
    asm volatile("{\n\t.reg .pred p;\n\t"                                     \
        "mbarrier.try_wait.parity.acquire.cta.shared::cta.b64 p, [%1], %2;\n\t" \
        "selp.b32 %0, 1, 0, p;\n\t}"                                          \
        : "=r"(_d) : "r"(_m), "r"(_p) : "memory");                            \
    if (!_d) {                                                                \
        asm volatile("{\n\t.reg .pred P1;\n\t"                                \
            "WL_%=:\n\t"                                                      \
            "mbarrier.try_wait.parity.acquire.cta.shared::cta.b64 P1, [%0], %1, 0x989680;\n\t" \
            "@P1 bra.uni WD_%=;\n\tbra.uni WL_%=;\n\tWD_%=:\n\t}"             \
            :: "r"(_m), "r"(_p) : "memory");                                  \
    }                                                                         \
} while (0)

__device__ __forceinline__ void bulk_g2s(uint32_t smem, const void* g,
                                         uint32_t bytes, uint32_t mbar) {
    asm volatile(
        "cp.async.bulk.shared::cta.global.mbarrier::complete_tx::bytes [%0], [%1], %2, [%3];"
        :: "r"(smem), "l"(g), "r"(bytes), "r"(mbar) : "memory");
}

__device__ __forceinline__ void mma16(float* d, const uint4& a, uint32_t b0, uint32_t b1) {
    asm volatile(
        "mma.sync.aligned.m16n8k16.row.col.f32.f16.f16.f32 "
        "{%0,%1,%2,%3},{%4,%5,%6,%7},{%8,%9},{%0,%1,%2,%3};"
        : "+f"(d[0]), "+f"(d[1]), "+f"(d[2]), "+f"(d[3])
        : "r"(a.x), "r"(a.y), "r"(a.z), "r"(a.w), "r"(b0), "r"(b1));
}

// ---------------- init ----------------
__global__ void init_state_kernel() {
    int idx = blockIdx.x * blockDim.x + threadIdx.x;
    if (idx < 2 * BH) g_c[idx] = 0.f;
}

// ---------------- M = enc_W @ Wih0^T (rank-2 folding), c0 = enc_b @ Wih0^T --
__global__ void compute_M_kernel(const float* __restrict__ enc_W,
                                 const float* __restrict__ enc_b,
                                 const float* __restrict__ Wih) {
    __shared__ float red[3][256];
    int r = blockIdx.x;                  // 0..2047 (permuted row 4j+g)
    int g = r & 3, j = r >> 2;
    const float* wrow = Wih + (size_t)(g * HID + j) * HID;   // layer 0
    float s0 = 0.f, s1 = 0.f, s2 = 0.f;
    for (int k = threadIdx.x; k < HID; k += 256) {
        float w = wrow[k];
        s0 += enc_W[k] * w;
        s1 += enc_W[HID + k] * w;
        s2 += enc_b[k] * w;
    }
    red[0][threadIdx.x] = s0; red[1][threadIdx.x] = s1; red[2][threadIdx.x] = s2;
    __syncthreads();
    for (int st = 128; st > 0; st >>= 1) {
        if (threadIdx.x < st) {
            red[0][threadIdx.x] += red[0][threadIdx.x + st];
            red[1][threadIdx.x] += red[1][threadIdx.x + st];
            red[2][threadIdx.x] += red[2][threadIdx.x + st];
        }
        __syncthreads();
    }
    if (threadIdx.x == 0) {
        g_M[r] = red[0][0];
        g_M[G4 + r] = red[1][0];
        g_M[2 * G4 + r] = red[2][0];
    }
}

// normalized inputs table: g_v01[(t*BATCH+b)*2 + d]
__global__ void v01_kernel(const float* __restrict__ obsVel,
                           const float* __restrict__ mean,
                           const float* __restrict__ stdv) {
    int i = blockIdx.x * blockDim.x + threadIdx.x;
    if (i >= OBSTEPS * BATCH * 2) return;
    int d = i & 1, tb = i >> 1;
    int b = tb % BATCH, t = tb / BATCH;
    g_v01[i] = (obsVel[(b * OBS_N + t) * 2 + d] - mean[d]) / stdv[d];
}

// ---------------- weight / bias permutes ----------------
__global__ void permute_w_kernel(const float* __restrict__ Wih,
                                 const float* __restrict__ Whh) {
    int i = blockIdx.x * blockDim.x + threadIdx.x;
    if (i >= 2 * G4 * 1024) return;
    int k = i & 1023;
    int r = (i >> 10) & 2047;
    int l = i >> 21;
    int g = r & 3, j = r >> 2;
    int oldrow = l * G4 + g * HID + j;
    float val = (k < HID) ? Wih[(size_t)oldrow * HID + k]
                          : Whh[(size_t)oldrow * HID + (k - HID)];
    int nt = r >> 8, rn = r & 255, kb = k >> 6;
    g_Wp[(size_t)l * WIMGH + (size_t)(nt * 16 + kb) * BBLKH + b_off_h(rn, k & 63)]
        = __float2half_rn(val);
}

__global__ void permute_b_kernel(const float* __restrict__ bih,
                                 const float* __restrict__ bhh) {
    int idx = blockIdx.x * blockDim.x + threadIdx.x;
    if (idx >= 2 * G4) return;
    int l = idx >> 11, r = idx & 2047;
    int g = r & 3, j = r >> 2;
    int old = l * G4 + g * HID + j;
    g_bias[idx] = bih[old] + bhh[old];
}

// ---------------- t=0 layer-0: gates = rank-2 x + bias (h=c=0, no GEMM) ----
__global__ void step0_l0_kernel() {
    int idx = blockIdx.x * blockDim.x + threadIdx.x;   // (b, j)
    if (idx >= BH) return;
    int b = idx / HID, j = idx % HID;
    float2 v = *(const float2*)&g_v01[b * 2];          // t = 0
    float4 m0 = *(const float4*)&g_M[4 * j];
    float4 m1 = *(const float4*)&g_M[G4 + 4 * j];
    float4 c0 = *(const float4*)&g_M[2 * G4 + 4 * j];
    float4 bi = *(const float4*)&g_bias[4 * j];
    float gi = v.x * m0.x + v.y * m1.x + c0.x + bi.x;
    float gg = v.x * m0.z + v.y * m1.z + c0.z + bi.z;
    float go = v.x * m0.w + v.y * m1.w + c0.w + bi.w;
    float cn = fsigm(gi) * ftanh(gg);                  // c_prev = 0
    g_c[idx] = cn;
    float hv = fsigm(go) * ftanh(cn);
    int mt = b >> 7, row = b & 127;
    g_H[(size_t)(mt * 8 + (j >> 6)) * ABLKH + a_off_h(row, j & 63)]   // buf0 layer0
        = __float2half_rn(hv);
}

// ---------------- fused GEMM + LSTM (fp16 mma, shuffle epilogue) -----------
#define NSTG 3
#define STGB (ABLKB + BBLKB)                  /* 49152 */
#define SMEM_BYTES (1024 + NSTG * (int)STGB)  /* 148480 */

// job1 (blockIdx.y < 16): xsel/wbuf/layer/kb_lo..kb_hi/tstep/kdec.
// job2 (blockIdx.y >= 16, obs-phase fusion): layer 0, kb 8..16, H-half,
//   with wbuf2/tstep2; mt = blockIdx.y - 16.
__global__ __launch_bounds__(256, 1) void gemm_lstm_kernel(
    int xsel, int wbuf, int layer, int kb_lo, int kb_hi, int tstep, int kdec,
    int wbuf2, int tstep2, const float* __restrict__ dec_W)
{
    extern __shared__ char smem[];
    const uint32_t sb = smem_u32(smem);
    const uint32_t mb_full = sb + 16;
    const uint32_t stg0 = sb + 1024;

    const int tid = threadIdx.x;
    const int warp = tid >> 5;
    const int lane = tid & 31;
    const int wr = warp >> 2;
    const int wc = warp & 3;
    const int nt = blockIdx.x;      // 0..7
    int mt = blockIdx.y;

    if (mt >= 16) {                 // job2: obs l0 H-half of next step
        mt -= 16;
        xsel = 8; wbuf = wbuf2; layer = 0;
        kb_lo = 8; kb_hi = 16; tstep = tstep2; kdec = -1;
    }

    const char* Xb = (xsel == 7)
        ? (const char*)(g_H + (size_t)((wbuf ^ 1) * 2 + 1) * AIMGH)
        : (const char*)(g_H + (size_t)(wbuf * 2 + 0) * AIMGH);
    const char* Hb  = (const char*)(g_H + (size_t)((wbuf ^ 1) * 2 + layer) * AIMGH);
    __half*    Hout = g_H + (size_t)(wbuf * 2 + layer) * AIMGH;
    const char* Wb  = (const char*)(g_Wp + (size_t)layer * WIMGH);
    float*      cst = g_c + (size_t)layer * BH;
    const float* bias = g_bias + (size_t)layer * G4;

    if (tid == 0) {
        #pragma unroll
        for (int s = 0; s < NSTG; s++) MBARRIER_INIT(mb_full + s * 8, 1);
    }
    __syncthreads();

    auto issue = [&](int kb) {
        int s = (kb - kb_lo) % NSTG;
        uint32_t st = stg0 + s * STGB;
        const char* asrc = (kb < 8) ? (Xb + (size_t)(mt * 8 + kb) * ABLKB)
                                    : (Hb + (size_t)(mt * 8 + (kb - 8)) * ABLKB);
        const char* bsrc = Wb + (size_t)(nt * 16 + kb) * BBLKB;
        MBARRIER_EXPECT_TX(mb_full + s * 8, STGB);
        bulk_g2s(st,         asrc, ABLKB, mb_full + s * 8);
        bulk_g2s(st + ABLKB, bsrc, BBLKB, mb_full + s * 8);
    };

    if (tid == 0) { issue(kb_lo); issue(kb_lo + 1); }

    float acc[4][8][4];
    #pragma unroll
    for (int mi = 0; mi < 4; mi++)
        #pragma unroll
        for (int ni = 0; ni < 8; ni++)
            #pragma unroll
            for (int q = 0; q < 4; q++) acc[mi][ni][q] = 0.f;

    #pragma unroll 1
    for (int kb = kb_lo; kb < kb_hi; kb++) {
        int rel = kb - kb_lo;
        int s = rel % NSTG;
        __syncthreads();
        if (tid == 0 && kb + 2 < kb_hi) issue(kb + 2);
        MBARRIER_WAIT_PARITY(mb_full + s * 8, (rel / NSTG) & 1);

        const uint4* as4 = (const uint4*)(smem + 1024 + (size_t)s * STGB);
        const uint4* bs4 = (const uint4*)(smem + 1024 + (size_t)s * STGB + ABLKB);

        #pragma unroll
        for (int kp = 0; kp < 2; kp++) {
            uint4 bf[8];
            #pragma unroll
            for (int ni = 0; ni < 8; ni++)
                bf[ni] = bs4[(kp * 32 + wc * 8 + ni) * 32 + lane];
            #pragma unroll
            for (int kh = 0; kh < 2; kh++) {
                int ki = kp * 2 + kh;
                uint4 af[4];
                #pragma unroll
                for (int mi = 0; mi < 4; mi++)
                    af[mi] = as4[(ki * 8 + wr * 4 + mi) * 32 + lane];
                #pragma unroll
                for (int mi = 0; mi < 4; mi++)
                    #pragma unroll
                    for (int ni = 0; ni < 8; ni++) {
                        uint32_t b0 = kh ? bf[ni].z : bf[ni].x;
                        uint32_t b1 = kh ? bf[ni].w : bf[ni].y;
                        mma16(acc[mi][ni], af[mi], b0, b1);
                    }
            }
        }
    }

    // ---- shuffle epilogue: gates live in fragments; no smem roundtrip ----
    // acc quad (mi,ni): rows r0, r0+8; cols c0, c0+1 where
    //   r0 = wr*64 + mi*16 + (lane>>2),  c0 = wc*64 + ni*8 + (lane&3)*2
    // lane^1 partner holds the other gate pair of the SAME unit/rows.
    const int sub   = lane >> 2;
    const int par   = lane & 1;          // 0: row r0 (owns i,f); 1: row r0+8 (owns g,o)
    const int jpair = (lane >> 1) & 1;   // unit within the ni 8-col group

    #pragma unroll
    for (int mi = 0; mi < 4; mi++) {
        int row_l = wr * 64 + mi * 16 + sub + par * 8;   // local row 0..127
        int b = mt * 128 + row_l;
        float dd0 = 0.f, dd1 = 0.f;
        #pragma unroll
        for (int ni = 0; ni < 8; ni++) {
            float q0 = acc[mi][ni][0], q1 = acc[mi][ni][1];
            float q2 = acc[mi][ni][2], q3 = acc[mi][ni][3];
            float s0 = __shfl_xor_sync(0xffffffffu, q0, 1);
            float s1 = __shfl_xor_sync(0xffffffffu, q1, 1);
            float s2 = __shfl_xor_sync(0xffffffffu, q2, 1);
            float s3 = __shfl_xor_sync(0xffffffffu, q3, 1);
            float gi, gf, gg, go;
            if (par == 0) { gi = q0; gf = q1; gg = s0; go = s1; }
            else          { gi = s2; gf = s3; gg = q2; go = q3; }

            int jl = wc * 16 + ni * 2 + jpair;           // local unit 0..63
            int rb = nt * 256 + jl * 4;
            if (tstep >= 0) {
                float2 v = *(const float2*)&g_v01[(tstep * BATCH + b) * 2];
                float4 m0 = *(const float4*)&g_M[rb];
                float4 m1 = *(const float4*)&g_M[G4 + rb];
                float4 c0 = *(const float4*)&g_M[2 * G4 + rb];
                gi += v.x * m0.x + v.y * m1.x + c0.x;
                gf += v.x * m0.y + v.y * m1.y + c0.y;
                gg += v.x * m0.z + v.y * m1.z + c0.z;
                go += v.x * m0.w + v.y * m1.w + c0.w;
            }
            float4 bi = *(const float4*)&bias[rb];
            gi += bi.x; gf += bi.y; gg += bi.z; go += bi.w;

            int j_hid = nt * 64 + jl;
            size_t ci = (size_t)b * HID + j_hid;
            float cn = fsigm(gf) * cst[ci] + fsigm(gi) * ftanh(gg);
            cst[ci] = cn;
            float hv = fsigm(go) * ftanh(cn);
            Hout[(size_t)(mt * 8 + nt) * ABLKH + a_off_h(row_l, jl)] = __float2half_rn(hv);

            if (kdec >= 0) {
                dd0 += hv * dec_W[2 * j_hid];
                dd1 += hv * dec_W[2 * j_hid + 1];
            }
        }
        if (kdec >= 0) {
            // lanes xor 2 share the same row (adjacent unit pair) -> sum
            dd0 += __shfl_xor_sync(0xffffffffu, dd0, 2);
            dd1 += __shfl_xor_sync(0xffffffffu, dd1, 2);
            if ((lane & 2) == 0) {
                int part = nt * 4 + wc;                  // 0..31
                *(float2*)&g_velp[(((size_t)part * BATCH + b) * PRED_N + kdec) * 2]
                    = make_float2(dd0, dd1);
            }
        }
    }

    __syncthreads();
    if (tid == 0) {
        #pragma unroll
        for (int s = 0; s < NSTG; s++) MBARRIER_INVAL(mb_full + s * 8);
    }
}

// ---------------- finalize (sums decode partials deterministically) --------
__global__ void finalize_kernel(const float* __restrict__ obs,
                                const float* __restrict__ mean,
                                const float* __restrict__ stdv,
                                const float* __restrict__ dec_b,
                                float* __restrict__ out, int out_size) {
    int i = blockIdx.x * blockDim.x + threadIdx.x;
    if (i >= BATCH * 2) return;
    int b = i >> 1, d = i & 1;
    float acc = obs[(b * OBS_N + (OBS_N - 1)) * 2 + d];
    float s = stdv[d], m = mean[d], db = dec_b[d];
    const int VOFF = BATCH * PRED_N * 2;
    bool write_vel = (out_size >= 2 * VOFF);
    #pragma unroll 1
    for (int k = 0; k < PRED_N; k++) {
        float v = db;
        #pragma unroll
        for (int p = 0; p < NPART; p++)
            v += g_velp[(((size_t)p * BATCH + b) * PRED_N + k) * 2 + d];
        acc += v * s + m;
        out[(b * PRED_N + k) * 2 + d] = acc;
        if (write_vel) out[VOFF + (b * PRED_N + k) * 2 + d] = v;
    }
}

extern "C" void kernel_launch(void* const* d_in, const int* in_sizes, int n_in,
                              void* d_out, int out_size) {
    const float* obs    = (const float*)d_in[0];
    const float* obsVel = (const float*)d_in[1];
    const float* mean   = (const float*)d_in[2];
    const float* stdv   = (const float*)d_in[3];
    const float* enc_W  = (const float*)d_in[4];
    const float* enc_b  = (const float*)d_in[5];
    const float* dec_W  = (const float*)d_in[6];
    const float* dec_b  = (const float*)d_in[7];
    const float* Wih    = (const float*)d_in[8];
    const float* Whh    = (const float*)d_in[9];
    const float* bih    = (const float*)d_in[10];
    const float* bhh    = (const float*)d_in[11];

    cudaFuncSetAttribute(gemm_lstm_kernel,
                         cudaFuncAttributeMaxDynamicSharedMemorySize, SMEM_BYTES);

    init_state_kernel<<<(2 * BH + 255) / 256, 256>>>();
    compute_M_kernel<<<G4, 256>>>(enc_W, enc_b, Wih);
    v01_kernel<<<(OBSTEPS * BATCH * 2 + 255) / 256, 256>>>(obsVel, mean, stdv);
    permute_w_kernel<<<(2 * G4 * 1024 + 255) / 256, 256>>>(Wih, Whh);
    permute_b_kernel<<<(2 * G4 + 255) / 256, 256>>>(bih, bhh);

    dim3 g1(8, 16);     // single job
    dim3 g2(8, 32);     // fused: job1 + obs-l0-half job2

    // t=0: l0 -> elementwise; fused [ l1(0) X-half  |  l0(1) H-half ]
    step0_l0_kernel<<<(BH + 255) / 256, 256>>>();
    gemm_lstm_kernel<<<g2, 256, SMEM_BYTES>>>(8, 0, 1, 0, 8, -1, -1,
                                              /*wbuf2=*/1, /*tstep2=*/1, dec_W);
    // t=1..5: fused [ l1(t) full | l0(t+1) H-half ]
    for (int t = 1; t <= 5; t++) {
        int w = t & 1;
        gemm_lstm_kernel<<<g2, 256, SMEM_BYTES>>>(8, w, 1, 0, 16, -1, -1,
                                                  w ^ 1, t + 1, dec_W);
    }
    // t=6: l1 full alone (l0(7) depends on its h1)
    gemm_lstm_kernel<<<g1, 256, SMEM_BYTES>>>(8, 0, 1, 0, 16, -1, -1, 0, 0, dec_W);

    // pred phase: strict serial chain
    for (int t = OBSTEPS; t < NSTEPS; t++) {
        int w = t & 1;
        gemm_lstm_kernel<<<g1, 256, SMEM_BYTES>>>(7, w, 0, 0, 16, -1, -1, 0, 0, dec_W);
        gemm_lstm_kernel<<<g1, 256, SMEM_BYTES>>>(8, w, 1, 0, 16, -1, t - OBSTEPS,
                                                  0, 0, dec_W);
    }

    finalize_kernel<<<(BATCH * 2 + 255) / 256, 256>>>(obs, mean, stdv, dec_b,
                                                      (float*)d_out, out_size);
}

// round 15
// speedup vs baseline: 1.7747x; 1.7747x over previous
#include <cuda_runtime.h>
#include <cuda_fp16.h>
#include <cstdint>
#include <cstddef>

#define BATCH   2048
#define OBS_N   8
#define PRED_N  12
#define HID     512
#define G4      2048
#define NSTEPS  19
#define OBSTEPS 7
#define BH      (BATCH*HID)

// fp16 fragment-packed image geometry (BK = 64)
#define ABLKH   8192
#define ABLKB   16384u
#define AIMGH   (16*8*ABLKH)
#define BBLKH   16384
#define BBLKB   32768u
#define WIMGH   (8*16*BBLKH)

// ---------------- scratch ----------------
__device__ __align__(1024) __half g_H[4 * AIMGH];     // [buf(2)][layer(2)]
__device__ __align__(1024) __half g_Wp[2 * WIMGH];
__device__ float g_M[3 * G4];                         // M0,M1,c0 (permuted rows)
__device__ float g_v01[OBSTEPS * BATCH * 2];          // normalized inputs per (t,b)
__device__ float g_c[2 * BH];
__device__ float g_bias[2 * G4];
__device__ float g_velp[16 * BATCH * PRED_N * 2];     // decode partials [part][b][k][d]

// ---------------- helpers ----------------
__device__ __forceinline__ uint32_t smem_u32(const void* p) {
    uint32_t a;
    asm("{ .reg .u64 t; cvta.to.shared.u64 t, %1; cvt.u32.u64 %0, t; }" : "=r"(a) : "l"(p));
    return a;
}
__device__ __forceinline__ float fsigm(float x) {
    return __fdividef(1.0f, 1.0f + __expf(-x));
}
__device__ __forceinline__ float ftanh(float x) {
    float a = fabsf(x);
    float t = 1.0f - __fdividef(2.0f, __expf(2.0f * a) + 1.0f);
    return copysignf(t, x);
}
// A (m16n8k16 row-major) half-index within a 128x64 block (tile = 256 halfs)
__device__ __forceinline__ int a_off_h(int row, int k) {
    int mi = row >> 4, r = row & 15;
    int ki = k >> 4,  kk = k & 15;
    int tile = ki * 8 + mi;
    int lane = (r & 7) * 4 + ((kk & 7) >> 1);
    int sel  = ((r >> 3) & 1) + ((kk >> 3) << 1);
    return tile * 256 + lane * 8 + sel * 2 + (kk & 1);
}
// B (m16n8k16 col) half-index within a 256x64 block, k32-paired per uint4
__device__ __forceinline__ int b_off_h(int rn, int k) {
    int kp = k >> 5, k32 = k & 31;
    int ki_in = k32 >> 4, kk = k32 & 15;
    int tile = kp * 32 + (rn >> 3);
    int lane = (rn & 7) * 4 + ((kk & 7) >> 1);
    int sel  = ki_in * 2 + (kk >> 3);
    return tile * 256 + lane * 8 + sel * 2 + (kk & 1);
}

#define MBARRIER_INIT(addr, cnt) \
    asm volatile("mbarrier.init.shared.b64 [%0], %1;" :: "r"(addr), "r"(cnt) : "memory")
#define MBARRIER_INVAL(addr) \
    asm volatile("mbarrier.inval.shared.b64 [%0];" :: "r"(addr) : "memory")
#define MBARRIER_EXPECT_TX(addr, bytes) \
    asm volatile("mbarrier.arrive.expect_tx.shared.b64 _, [%0], %1;" :: "r"(addr), "r"(bytes) : "memory")
#define MBARRIER_WAIT_PARITY(addr, ph) do {                                   \
    uint32_t _m = (addr), _p = (ph), _d;                                      \
    asm volatile("{\n\t.reg .pred p;\n\t"                                     \
        "mbarrier.try_wait.parity.acquire.cta.shared::cta.b64 p, [%1], %2;\n\t" \
        "selp.b32 %0, 1, 0, p;\n\t}"                                          \
        : "=r"(_d) : "r"(_m), "r"(_p) : "memory");                            \
    if (!_d) {                                                                \
        asm volatile("{\n\t.reg .pred P1;\n\t"                                \
            "WL_%=:\n\t"                                                      \
            "mbarrier.try_wait.parity.acquire.cta.shared::cta.b64 P1, [%0], %1, 0x989680;\n\t" \
            "@P1 bra.uni WD_%=;\n\tbra.uni WL_%=;\n\tWD_%=:\n\t}"             \
            :: "r"(_m), "r"(_p) : "memory");                                  \
    }                                                                         \
} while (0)

__device__ __forceinline__ void bulk_g2s(uint32_t smem, const void* g,
                                         uint32_t bytes, uint32_t mbar) {
    asm volatile(
        "cp.async.bulk.shared::cta.global.mbarrier::complete_tx::bytes [%0], [%1], %2, [%3];"
        :: "r"(smem), "l"(g), "r"(bytes), "r"(mbar) : "memory");
}

__device__ __forceinline__ void mma16(float* d, const uint4& a, uint32_t b0, uint32_t b1) {
    asm volatile(
        "mma.sync.aligned.m16n8k16.row.col.f32.f16.f16.f32 "
        "{%0,%1,%2,%3},{%4,%5,%6,%7},{%8,%9},{%0,%1,%2,%3};"
        : "+f"(d[0]), "+f"(d[1]), "+f"(d[2]), "+f"(d[3])
        : "r"(a.x), "r"(a.y), "r"(a.z), "r"(a.w), "r"(b0), "r"(b1));
}

// ---------------- init ----------------
__global__ void init_state_kernel() {
    int idx = blockIdx.x * blockDim.x + threadIdx.x;
    if (idx < 2 * BH) g_c[idx] = 0.f;
}

// ---------------- M = enc_W @ Wih0^T (rank-2 folding), c0 = enc_b @ Wih0^T --
__global__ void compute_M_kernel(const float* __restrict__ enc_W,
                                 const float* __restrict__ enc_b,
                                 const float* __restrict__ Wih) {
    __shared__ float red[3][256];
    int r = blockIdx.x;                  // 0..2047 (permuted row 4j+g)
    int g = r & 3, j = r >> 2;
    const float* wrow = Wih + (size_t)(g * HID + j) * HID;   // layer 0
    float s0 = 0.f, s1 = 0.f, s2 = 0.f;
    for (int k = threadIdx.x; k < HID; k += 256) {
        float w = wrow[k];
        s0 += enc_W[k] * w;
        s1 += enc_W[HID + k] * w;
        s2 += enc_b[k] * w;
    }
    red[0][threadIdx.x] = s0; red[1][threadIdx.x] = s1; red[2][threadIdx.x] = s2;
    __syncthreads();
    for (int st = 128; st > 0; st >>= 1) {
        if (threadIdx.x < st) {
            red[0][threadIdx.x] += red[0][threadIdx.x + st];
            red[1][threadIdx.x] += red[1][threadIdx.x + st];
            red[2][threadIdx.x] += red[2][threadIdx.x + st];
        }
        __syncthreads();
    }
    if (threadIdx.x == 0) {
        g_M[r] = red[0][0];
        g_M[G4 + r] = red[1][0];
        g_M[2 * G4 + r] = red[2][0];
    }
}

// normalized inputs table: g_v01[(t*BATCH+b)*2 + d]
__global__ void v01_kernel(const float* __restrict__ obsVel,
                           const float* __restrict__ mean,
                           const float* __restrict__ stdv) {
    int i = blockIdx.x * blockDim.x + threadIdx.x;
    if (i >= OBSTEPS * BATCH * 2) return;
    int d = i & 1, tb = i >> 1;
    int b = tb % BATCH, t = tb / BATCH;
    g_v01[i] = (obsVel[(b * OBS_N + t) * 2 + d] - mean[d]) / stdv[d];
}

// ---------------- weight / bias permutes ----------------
__global__ void permute_w_kernel(const float* __restrict__ Wih,
                                 const float* __restrict__ Whh) {
    int i = blockIdx.x * blockDim.x + threadIdx.x;
    if (i >= 2 * G4 * 1024) return;
    int k = i & 1023;
    int r = (i >> 10) & 2047;
    int l = i >> 21;
    int g = r & 3, j = r >> 2;
    int oldrow = l * G4 + g * HID + j;
    float val = (k < HID) ? Wih[(size_t)oldrow * HID + k]
                          : Whh[(size_t)oldrow * HID + (k - HID)];
    int nt = r >> 8, rn = r & 255, kb = k >> 6;
    g_Wp[(size_t)l * WIMGH + (size_t)(nt * 16 + kb) * BBLKH + b_off_h(rn, k & 63)]
        = __float2half_rn(val);
}

__global__ void permute_b_kernel(const float* __restrict__ bih,
                                 const float* __restrict__ bhh) {
    int idx = blockIdx.x * blockDim.x + threadIdx.x;
    if (idx >= 2 * G4) return;
    int l = idx >> 11, r = idx & 2047;
    int g = r & 3, j = r >> 2;
    int old = l * G4 + g * HID + j;
    g_bias[idx] = bih[old] + bhh[old];
}

// ---------------- t=0 layer-0: gates = rank-2 x + bias (h=c=0, no GEMM) ----
__global__ void step0_l0_kernel() {
    int idx = blockIdx.x * blockDim.x + threadIdx.x;   // (b, j)
    if (idx >= BH) return;
    int b = idx / HID, j = idx % HID;
    float2 v = *(const float2*)&g_v01[b * 2];          // t = 0
    float4 m0 = *(const float4*)&g_M[4 * j];
    float4 m1 = *(const float4*)&g_M[G4 + 4 * j];
    float4 c0 = *(const float4*)&g_M[2 * G4 + 4 * j];
    float4 bi = *(const float4*)&g_bias[4 * j];
    float gi = v.x * m0.x + v.y * m1.x + c0.x + bi.x;
    float gg = v.x * m0.z + v.y * m1.z + c0.z + bi.z;
    float go = v.x * m0.w + v.y * m1.w + c0.w + bi.w;
    float cn = fsigm(gi) * ftanh(gg);                  // c_prev = 0
    g_c[idx] = cn;
    float hv = fsigm(go) * ftanh(cn);
    int mt = b >> 7, row = b & 127;
    g_H[(size_t)(mt * 8 + (j >> 6)) * ABLKH + a_off_h(row, j & 63)]   // buf0 layer0
        = __float2half_rn(hv);
}

// ---------------- fused GEMM + LSTM (fp16 mma, 2 sequential jobs) ----------
#define NSTG 3
#define STGB (ABLKB + BBLKB)                  /* 49152 */
#define SMEM_BYTES (1024 + NSTG * (int)STGB)  /* 148480 */
#define CSTR 260

// job1: xsel/wbuf/layer/kb_lo..kb_hi/tstep/kdec.
// job2 (optional, obs fusion): layer 0, kb 8..16 H-half, wbuf2/tstep2.
__global__ __launch_bounds__(256, 1) void gemm_lstm_kernel(
    int xsel, int wbuf, int layer, int kb_lo, int kb_hi, int tstep, int kdec,
    int has_job2, int wbuf2, int tstep2, const float* __restrict__ dec_W)
{
    extern __shared__ char smem[];
    const uint32_t sb = smem_u32(smem);
    const uint32_t mb_full = sb + 16;
    const uint32_t stg0 = sb + 1024;

    const int tid = threadIdx.x;
    const int warp = tid >> 5;
    const int lane = tid & 31;
    const int wr = warp >> 2;
    const int wc = warp & 3;
    const int nt = blockIdx.x;      // 0..7
    const int mt = blockIdx.y;      // 0..15

    if (tid == 0) {
        #pragma unroll
        for (int s = 0; s < NSTG; s++) MBARRIER_INIT(mb_full + s * 8, 1);
    }
    __syncthreads();

    // run one GEMM+cell job; slab counter q continues across jobs.
    auto run_job = [&](int jxsel, int jwbuf, int jlayer, int jlo, int jhi,
                       int jtstep, int jkdec, int q0) -> int {
        const char* Xb = (jxsel == 7)
            ? (const char*)(g_H + (size_t)((jwbuf ^ 1) * 2 + 1) * AIMGH)
            : (const char*)(g_H + (size_t)(jwbuf * 2 + 0) * AIMGH);
        const char* Hb  = (const char*)(g_H + (size_t)((jwbuf ^ 1) * 2 + jlayer) * AIMGH);
        __half*    Hout = g_H + (size_t)(jwbuf * 2 + jlayer) * AIMGH;
        const char* Wb  = (const char*)(g_Wp + (size_t)jlayer * WIMGH);
        float*      cst = g_c + (size_t)jlayer * BH;
        const float* bias = g_bias + (size_t)jlayer * G4;

        auto issue = [&](int kb, int q) {
            int s = q % NSTG;
            uint32_t st = stg0 + s * STGB;
            const char* asrc = (kb < 8) ? (Xb + (size_t)(mt * 8 + kb) * ABLKB)
                                        : (Hb + (size_t)(mt * 8 + (kb - 8)) * ABLKB);
            const char* bsrc = Wb + (size_t)(nt * 16 + kb) * BBLKB;
            MBARRIER_EXPECT_TX(mb_full + s * 8, STGB);
            bulk_g2s(st,         asrc, ABLKB, mb_full + s * 8);
            bulk_g2s(st + ABLKB, bsrc, BBLKB, mb_full + s * 8);
        };

        if (tid == 0) { issue(jlo, q0); issue(jlo + 1, q0 + 1); }

        float acc[4][8][4];
        #pragma unroll
        for (int mi = 0; mi < 4; mi++)
            #pragma unroll
            for (int ni = 0; ni < 8; ni++)
                #pragma unroll
                for (int q = 0; q < 4; q++) acc[mi][ni][q] = 0.f;

        #pragma unroll 1
        for (int kb = jlo; kb < jhi; kb++) {
            int q = q0 + (kb - jlo);
            int s = q % NSTG;
            __syncthreads();
            if (tid == 0 && kb + 2 < jhi) issue(kb + 2, q + 2);
            MBARRIER_WAIT_PARITY(mb_full + s * 8, (q / NSTG) & 1);

            const uint4* as4 = (const uint4*)(smem + 1024 + (size_t)s * STGB);
            const uint4* bs4 = (const uint4*)(smem + 1024 + (size_t)s * STGB + ABLKB);

            #pragma unroll
            for (int kp = 0; kp < 2; kp++) {
                uint4 bf[8];
                #pragma unroll
                for (int ni = 0; ni < 8; ni++)
                    bf[ni] = bs4[(kp * 32 + wc * 8 + ni) * 32 + lane];
                #pragma unroll
                for (int kh = 0; kh < 2; kh++) {
                    int ki = kp * 2 + kh;
                    uint4 af[4];
                    #pragma unroll
                    for (int mi = 0; mi < 4; mi++)
                        af[mi] = as4[(ki * 8 + wr * 4 + mi) * 32 + lane];
                    #pragma unroll
                    for (int mi = 0; mi < 4; mi++)
                        #pragma unroll
                        for (int ni = 0; ni < 8; ni++) {
                            uint32_t b0 = kh ? bf[ni].z : bf[ni].x;
                            uint32_t b1 = kh ? bf[ni].w : bf[ni].y;
                            mma16(acc[mi][ni], af[mi], b0, b1);
                        }
                }
            }
        }
        __syncthreads();

        // ---- Cs epilogue (coalesced cell pass), identical math to R12 ----
        float* Cs = (float*)(smem + 1024);
        #pragma unroll
        for (int mi = 0; mi < 4; mi++)
            #pragma unroll
            for (int ni = 0; ni < 8; ni++) {
                int row0 = wr * 64 + mi * 16 + (lane >> 2);
                int col  = wc * 64 + ni * 8 + (lane & 3) * 2;
                *(float2*)&Cs[row0 * CSTR + col]       = make_float2(acc[mi][ni][0], acc[mi][ni][1]);
                *(float2*)&Cs[(row0 + 8) * CSTR + col] = make_float2(acc[mi][ni][2], acc[mi][ni][3]);
            }
        __syncthreads();

        #pragma unroll 1
        for (int it = 0; it < 32; it++) {
            int idx = tid + it * 256;
            int bl = idx >> 6, jl = idx & 63;
            float4 gq = *(const float4*)&Cs[bl * CSTR + jl * 4];
            int rb = nt * 256 + jl * 4;
            if (jtstep >= 0) {
                int b = mt * 128 + bl;
                float2 v = *(const float2*)&g_v01[(jtstep * BATCH + b) * 2];
                float4 m0 = *(const float4*)&g_M[rb];
                float4 m1 = *(const float4*)&g_M[G4 + rb];
                float4 c0 = *(const float4*)&g_M[2 * G4 + rb];
                gq.x += v.x * m0.x + v.y * m1.x + c0.x;
                gq.y += v.x * m0.y + v.y * m1.y + c0.y;
                gq.z += v.x * m0.z + v.y * m1.z + c0.z;
                gq.w += v.x * m0.w + v.y * m1.w + c0.w;
            }
            float gi = gq.x + bias[rb + 0];
            float gf = gq.y + bias[rb + 1];
            float gg = gq.z + bias[rb + 2];
            float go = gq.w + bias[rb + 3];
            int j = nt * 64 + jl;
            size_t ci = (size_t)(mt * 128 + bl) * HID + j;
            float cn = fsigm(gf) * cst[ci] + fsigm(gi) * ftanh(gg);
            cst[ci] = cn;
            float hv = fsigm(go) * ftanh(cn);
            Hout[(size_t)(mt * 8 + (j >> 6)) * ABLKH + a_off_h(bl, j & 63)] = __float2half_rn(hv);

            if (jkdec >= 0) {
                float d0 = hv * dec_W[2 * j];
                float d1 = hv * dec_W[2 * j + 1];
                #pragma unroll
                for (int o = 16; o > 0; o >>= 1) {
                    d0 += __shfl_down_sync(0xffffffffu, d0, o);
                    d1 += __shfl_down_sync(0xffffffffu, d1, o);
                }
                if (lane == 0) {
                    int b = mt * 128 + bl;
                    int part = nt * 2 + (warp & 1);
                    *(float2*)&g_velp[(((size_t)part * BATCH + b) * PRED_N + jkdec) * 2]
                        = make_float2(d0, d1);
                }
            }
        }
        __syncthreads();   // Cs fully consumed before any later stage writes
        return q0 + (jhi - jlo);
    };

    int q = run_job(xsel, wbuf, layer, kb_lo, kb_hi, tstep, kdec, 0);
    if (has_job2)
        run_job(8, wbuf2, 0, 8, 16, tstep2, -1, q);

    if (tid == 0) {
        #pragma unroll
        for (int s = 0; s < NSTG; s++) MBARRIER_INVAL(mb_full + s * 8);
    }
}

// ---------------- finalize (sums decode partials deterministically) --------
__global__ void finalize_kernel(const float* __restrict__ obs,
                                const float* __restrict__ mean,
                                const float* __restrict__ stdv,
                                const float* __restrict__ dec_b,
                                float* __restrict__ out, int out_size) {
    int i = blockIdx.x * blockDim.x + threadIdx.x;
    if (i >= BATCH * 2) return;
    int b = i >> 1, d = i & 1;
    float acc = obs[(b * OBS_N + (OBS_N - 1)) * 2 + d];
    float s = stdv[d], m = mean[d], db = dec_b[d];
    const int VOFF = BATCH * PRED_N * 2;
    bool write_vel = (out_size >= 2 * VOFF);
    #pragma unroll 1
    for (int k = 0; k < PRED_N; k++) {
        float v = db;
        #pragma unroll
        for (int p = 0; p < 16; p++)
            v += g_velp[(((size_t)p * BATCH + b) * PRED_N + k) * 2 + d];
        acc += v * s + m;
        out[(b * PRED_N + k) * 2 + d] = acc;
        if (write_vel) out[VOFF + (b * PRED_N + k) * 2 + d] = v;
    }
}

extern "C" void kernel_launch(void* const* d_in, const int* in_sizes, int n_in,
                              void* d_out, int out_size) {
    const float* obs    = (const float*)d_in[0];
    const float* obsVel = (const float*)d_in[1];
    const float* mean   = (const float*)d_in[2];
    const float* stdv   = (const float*)d_in[3];
    const float* enc_W  = (const float*)d_in[4];
    const float* enc_b  = (const float*)d_in[5];
    const float* dec_W  = (const float*)d_in[6];
    const float* dec_b  = (const float*)d_in[7];
    const float* Wih    = (const float*)d_in[8];
    const float* Whh    = (const float*)d_in[9];
    const float* bih    = (const float*)d_in[10];
    const float* bhh    = (const float*)d_in[11];

    cudaFuncSetAttribute(gemm_lstm_kernel,
                         cudaFuncAttributeMaxDynamicSharedMemorySize, SMEM_BYTES);

    init_state_kernel<<<(2 * BH + 255) / 256, 256>>>();
    compute_M_kernel<<<G4, 256>>>(enc_W, enc_b, Wih);
    v01_kernel<<<(OBSTEPS * BATCH * 2 + 255) / 256, 256>>>(obsVel, mean, stdv);
    permute_w_kernel<<<(2 * G4 * 1024 + 255) / 256, 256>>>(Wih, Whh);
    permute_b_kernel<<<(2 * G4 + 255) / 256, 256>>>(bih, bhh);

    dim3 gg(8, 16);     // 128 CTAs, one wave always

    // t=0: l0 elementwise; fused launch [ l1(0) X-half ; l0(1) H-half ]
    step0_l0_kernel<<<(BH + 255) / 256, 256>>>();
    gemm_lstm_kernel<<<gg, 256, SMEM_BYTES>>>(8, 0, 1, 0, 8, -1, -1,
                                              1, /*wbuf2=*/1, /*tstep2=*/1, dec_W);
    // t=1..5: fused [ l1(t) full ; l0(t+1) H-half ]
    for (int t = 1; t <= 5; t++) {
        int w = t & 1;
        gemm_lstm_kernel<<<gg, 256, SMEM_BYTES>>>(8, w, 1, 0, 16, -1, -1,
                                                  1, w ^ 1, t + 1, dec_W);
    }
    // t=6: l1 full alone (l0(7) needs its h1)
    gemm_lstm_kernel<<<gg, 256, SMEM_BYTES>>>(8, 0, 1, 0, 16, -1, -1, 0, 0, 0, dec_W);

    // pred phase: strict serial chain
    for (int t = OBSTEPS; t < NSTEPS; t++) {
        int w = t & 1;
        gemm_lstm_kernel<<<gg, 256, SMEM_BYTES>>>(7, w, 0, 0, 16, -1, -1, 0, 0, 0, dec_W);
        gemm_lstm_kernel<<<gg, 256, SMEM_BYTES>>>(8, w, 1, 0, 16, -1, t - OBSTEPS,
                                                  0, 0, 0, dec_W);
    }

    finalize_kernel<<<(BATCH * 2 + 255) / 256, 256>>>(obs, mean, stdv, dec_b,
                                                      (float*)d_out, out_size);
}